// round 15
// baseline (speedup 1.0000x reference)
#include <cuda_runtime.h>
#include <cuda_fp16.h>
#include <math.h>

// ---------------------------------------------------------------------------
// NanoGPT forward (B=4, T=1024, E=1024, H=16, L=6, V=50257)
// R14: R13 + double-buffered flash-attention kv-loop (K via cp.async x2,
//      V via register prefetch) — kv load latency fully overlapped.
// ---------------------------------------------------------------------------

#define NB     4
#define NT     1024
#define NE     1024
#define NH     16
#define HDIM   64
#define NLAYER 6
#define NV     50257
#define NM     (NB * NT)
#define NBLK64 786                  // ceil(NV/64)
#define LSE_STRIDE 1600
#define LN_EPS 1e-5f

// ------------------------------- scratch -----------------------------------
__device__ float  g_x  [NM * NE];
__device__ __half g_h  [NM * NE];
__device__ __half g_qkv[NM * 3 * NE];
__device__ __half g_y  [NM * NE];
__device__ __half g_fc [NM * 4 * NE];
__device__ float  g_att[(size_t)1024 * NV];        // logits chunk / lse scratch
__device__ float  g_nll[NM];

__device__ __half w_attn[(size_t)NLAYER * 3 * NE * NE];
__device__ __half w_proj[(size_t)NLAYER * NE * NE];
__device__ __half w_fc  [(size_t)NLAYER * 4 * NE * NE];
__device__ __half w_fcp [(size_t)NLAYER * NE * 4 * NE];
__device__ __half w_lm  [(size_t)NV * NE];

// ----------------------------- helpers --------------------------------------
__device__ __forceinline__ void mma16(float* c, const unsigned* a, const unsigned* b) {
    asm volatile(
        "mma.sync.aligned.m16n8k16.row.col.f32.f16.f16.f32 "
        "{%0,%1,%2,%3}, {%4,%5,%6,%7}, {%8,%9}, {%0,%1,%2,%3};"
        : "+f"(c[0]), "+f"(c[1]), "+f"(c[2]), "+f"(c[3])
        : "r"(a[0]), "r"(a[1]), "r"(a[2]), "r"(a[3]), "r"(b[0]), "r"(b[1]));
}

__device__ __forceinline__ void cpa16(void* dst, const void* src, bool full) {
    unsigned d = (unsigned)__cvta_generic_to_shared(dst);
    int sz = full ? 16 : 0;
    asm volatile("cp.async.cg.shared.global [%0], [%1], 16, %2;"
                 :: "r"(d), "l"(src), "r"(sz));
}

__device__ __forceinline__ unsigned lds_u32(const __half* p) {
    return *(const unsigned*)p;
}

__device__ __forceinline__ float gelu_f(float x) {
    return 0.5f * x * (1.0f + erff(x * 0.70710678118654752f));
}

// --------------------------- f32 -> f16 convert ------------------------------
__global__ void f2h_kernel(const float4* __restrict__ src,
                           __half2* __restrict__ dst, int n4) {
    int i = blockIdx.x * blockDim.x + threadIdx.x;
    if (i < n4) {
        float4 v = src[i];
        dst[2 * i]     = __floats2half2_rn(v.x, v.y);
        dst[2 * i + 1] = __floats2half2_rn(v.z, v.w);
    }
}

// ------------------------------- embed -------------------------------------
__global__ void embed_kernel(const int* __restrict__ idx,
                             const float* __restrict__ wte,
                             const float* __restrict__ wpe) {
    int row = blockIdx.x;
    int t   = row % NT;
    int tok = idx[row];
    const float* s = wte + (size_t)tok * NE;
    const float* p = wpe + (size_t)t * NE;
    float* o = g_x + (size_t)row * NE;
    for (int c = threadIdx.x; c < NE; c += blockDim.x)
        o[c] = s[c] + p[c];
}

// ------------------------------ layernorm -----------------------------------
// single pass: 256 threads x 4 elements in registers; 2 barriers.
__global__ void ln_kernel(const float* __restrict__ in,
                          const float* __restrict__ w,
                          const float* __restrict__ b,
                          __half* __restrict__ out) {
    int row = blockIdx.x;
    int tid = threadIdx.x;
    const float* x = in + (size_t)row * NE;
    __half* o = out + (size_t)row * NE;

    float4 v = *(const float4*)(x + tid * 4);
    float s  = v.x + v.y + v.z + v.w;
    float s2 = v.x * v.x + v.y * v.y + v.z * v.z + v.w * v.w;

#pragma unroll
    for (int d = 16; d > 0; d >>= 1) {
        s  += __shfl_xor_sync(0xffffffffu, s,  d);
        s2 += __shfl_xor_sync(0xffffffffu, s2, d);
    }

    __shared__ float ws[8], ws2[8];
    __shared__ float s_mu, s_rstd;
    int wid = tid >> 5, lane = tid & 31;
    if (lane == 0) { ws[wid] = s; ws2[wid] = s2; }
    __syncthreads();
    if (tid == 0) {
        float ts = 0.f, ts2 = 0.f;
#pragma unroll
        for (int k = 0; k < 8; k++) { ts += ws[k]; ts2 += ws2[k]; }
        float mu  = ts * (1.0f / NE);
        float var = ts2 * (1.0f / NE) - mu * mu;
        s_mu   = mu;
        s_rstd = rsqrtf(var + LN_EPS);
    }
    __syncthreads();
    float mu = s_mu, rstd = s_rstd;

    const float4 wv = *(const float4*)(w + tid * 4);
    const float4 bv = *(const float4*)(b + tid * 4);
    __half2 h0 = __floats2half2_rn((v.x - mu) * rstd * wv.x + bv.x,
                                   (v.y - mu) * rstd * wv.y + bv.y);
    __half2 h1 = __floats2half2_rn((v.z - mu) * rstd * wv.z + bv.z,
                                   (v.w - mu) * rstd * wv.w + bv.w);
    *(__half2*)(o + tid * 4)     = h0;
    *(__half2*)(o + tid * 4 + 2) = h1;
}

// ------------------------- fp16 tensor-core GEMM -----------------------------
// (R10/R13 kernel — 2-stage BK=64, warp tile 64x64, 2 CTAs/SM; unchanged)
#define SPAD   72
#define STG_H  (2 * 128 * SPAD)

template <int EPI, int RAST>
__global__ void __launch_bounds__(128, 2)
mma_gemm(const __half* __restrict__ A, const __half* __restrict__ B,
         void* __restrict__ Cv,
         int M, int N, int K, int lda, int ldb, int ldc) {
    extern __shared__ __half sh[];
    const int bxn  = RAST ? blockIdx.y : blockIdx.x;
    const int bxm  = RAST ? blockIdx.x : blockIdx.y;
    const int bm   = bxm * 128;
    const int bn   = bxn * 128;
    const int tid  = threadIdx.x;
    const int lane = tid & 31;
    const int wid  = tid >> 5;
    const int wm   = (wid >> 1) * 64;
    const int wn   = (wid & 1) * 64;
    const int lr   = lane >> 2;
    const int lc   = lane & 3;

    const __half* Asrc[8];
    const __half* Bsrc[8];
    bool bval[8];
    int  dOff[8];
#pragma unroll
    for (int i = 0; i < 8; i++) {
        int c = tid + i * 128;
        int row = c >> 3, ch = (c & 7) * 8;
        dOff[i] = row * SPAD + ch;
        Asrc[i] = A + (size_t)(bm + row) * lda + ch;
        bval[i] = (bn + row) < N;
        Bsrc[i] = B + (size_t)min(bn + row, N - 1) * ldb + ch;
    }

    float acc[4][8][4];
#pragma unroll
    for (int i = 0; i < 4; i++)
#pragma unroll
        for (int j = 0; j < 8; j++)
#pragma unroll
            for (int q = 0; q < 4; q++) acc[i][j][q] = 0.f;

    const int KT = K >> 6;

    {
        __half* sA = sh;
        __half* sB = sh + 128 * SPAD;
#pragma unroll
        for (int i = 0; i < 8; i++) {
            cpa16(sA + dOff[i], Asrc[i], true);
            cpa16(sB + dOff[i], Bsrc[i], bval[i]);
        }
        asm volatile("cp.async.commit_group;");
    }

    for (int kt = 0; kt < KT; kt++) {
        int pf = kt + 1;
        if (pf < KT) {
            __half* sA = sh + (pf & 1) * STG_H;
            __half* sB = sA + 128 * SPAD;
            int k0 = pf * 64;
#pragma unroll
            for (int i = 0; i < 8; i++) {
                cpa16(sA + dOff[i], Asrc[i] + k0, true);
                cpa16(sB + dOff[i], Bsrc[i] + k0, bval[i]);
            }
        }
        asm volatile("cp.async.commit_group;");
        asm volatile("cp.async.wait_group 1;");
        __syncthreads();

        const __half* As = sh + (kt & 1) * STG_H;
        const __half* Bs = As + 128 * SPAD;
#pragma unroll
        for (int ks = 0; ks < 4; ks++) {
            const int k0 = ks * 16 + 2 * lc;
            unsigned afr[4][4], bfr[8][2];
#pragma unroll
            for (int i = 0; i < 4; i++) {
                const __half* p = &As[(wm + i * 16 + lr) * SPAD + k0];
                afr[i][0] = lds_u32(p);
                afr[i][1] = lds_u32(p + 8 * SPAD);
                afr[i][2] = lds_u32(p + 8);
                afr[i][3] = lds_u32(p + 8 * SPAD + 8);
            }
#pragma unroll
            for (int j = 0; j < 8; j++) {
                const __half* p = &Bs[(wn + j * 8 + lr) * SPAD + k0];
                bfr[j][0] = lds_u32(p);
                bfr[j][1] = lds_u32(p + 8);
            }
#pragma unroll
            for (int i = 0; i < 4; i++)
#pragma unroll
                for (int j = 0; j < 8; j++)
                    mma16(acc[i][j], afr[i], bfr[j]);
        }
        __syncthreads();
    }

#pragma unroll
    for (int i = 0; i < 4; i++) {
        int r0 = bm + wm + i * 16 + lr;
#pragma unroll
        for (int j = 0; j < 8; j++) {
            int c0 = bn + wn + j * 8 + (lc << 1);
            const float* a4 = acc[i][j];
            if (EPI == 0 || EPI == 4) {
                float* C0 = (float*)Cv + (size_t)r0 * ldc;
                float* C1 = C0 + (size_t)8 * ldc;
#pragma unroll
                for (int q = 0; q < 2; q++) {
                    int col = c0 + q;
                    if (col < N) { C0[col] = a4[q]; C1[col] = a4[q + 2]; }
                }
            } else if (EPI == 1) {
                __half* C0 = (__half*)Cv + (size_t)r0 * ldc;
                __half* C1 = C0 + (size_t)8 * ldc;
                *(__half2*)&C0[c0] = __floats2half2_rn(a4[0], a4[1]);
                *(__half2*)&C1[c0] = __floats2half2_rn(a4[2], a4[3]);
            } else if (EPI == 2) {
                __half* C0 = (__half*)Cv + (size_t)r0 * ldc;
                __half* C1 = C0 + (size_t)8 * ldc;
                *(__half2*)&C0[c0] = __floats2half2_rn(gelu_f(a4[0]), gelu_f(a4[1]));
                *(__half2*)&C1[c0] = __floats2half2_rn(gelu_f(a4[2]), gelu_f(a4[3]));
            } else if (EPI == 3) {
                float* C0 = (float*)Cv + (size_t)r0 * ldc;
                float* C1 = C0 + (size_t)8 * ldc;
                C0[c0] += a4[0]; C0[c0 + 1] += a4[1];
                C1[c0] += a4[2]; C1[c0 + 1] += a4[3];
            }
        }
    }

    if (EPI == 4) {
        int blk = (bn + wn) >> 6;
#pragma unroll
        for (int i = 0; i < 4; i++) {
#pragma unroll
            for (int hh = 0; hh < 2; hh++) {
                float lm_ = -1e30f;
#pragma unroll
                for (int j = 0; j < 8; j++) {
                    int c0 = bn + wn + j * 8 + (lc << 1);
                    float v0 = (c0     < N) ? acc[i][j][hh * 2]     : -1e30f;
                    float v1 = (c0 + 1 < N) ? acc[i][j][hh * 2 + 1] : -1e30f;
                    lm_ = fmaxf(lm_, fmaxf(v0, v1));
                }
                lm_ = fmaxf(lm_, __shfl_xor_sync(0xffffffffu, lm_, 1));
                lm_ = fmaxf(lm_, __shfl_xor_sync(0xffffffffu, lm_, 2));
                float ls = 0.f;
#pragma unroll
                for (int j = 0; j < 8; j++) {
                    int c0 = bn + wn + j * 8 + (lc << 1);
                    if (c0     < N) ls += __expf(acc[i][j][hh * 2]     - lm_);
                    if (c0 + 1 < N) ls += __expf(acc[i][j][hh * 2 + 1] - lm_);
                }
                ls += __shfl_xor_sync(0xffffffffu, ls, 1);
                ls += __shfl_xor_sync(0xffffffffu, ls, 2);
                if (lc == 0) {
                    int row = bm + wm + i * 16 + lr + hh * 8;
                    float* lse = g_att + (size_t)row * LSE_STRIDE + blk * 2;
                    lse[0] = lm_;
                    lse[1] = ls;
                }
            }
        }
    }
}

// --------------------------- flash attention ---------------------------------
// R14: double-buffered K (cp.async) and V (register prefetch + STS).
#define QP 72
#define VP 74
#define KBUF (64 * QP)
#define VBUF (64 * VP)
#define FA_SMEM ((2 * KBUF + 2 * VBUF) * (int)sizeof(__half))

__global__ void __launch_bounds__(256, 2)
flash_attn_kernel() {
    extern __shared__ __half fsh[];
    __half* sK  = fsh;                   // [2][64][QP]
    __half* sVt = fsh + 2 * KBUF;        // [2][64 hd][VP seq]

    const int qt  = blockIdx.x;
    const int bh  = blockIdx.y;
    const int b   = bh >> 4, h = bh & 15;
    const int tid = threadIdx.x;
    const int w   = tid >> 5;
    const int lane = tid & 31;
    const int lr  = lane >> 2;
    const int lc  = lane & 3;
    const int wrow = w * 16 + lr;

    const __half* base = g_qkv + (size_t)b * NT * 3 * NE + h * 64;

    // ---- stage Q (128 x 64) into sK area (stride QP), extract frags ----
    {
        const __half* Qg = base + (size_t)(qt * 128) * 3 * NE;
#pragma unroll
        for (int i = 0; i < 4; i++) {
            int idx = tid + i * 256;
            int row = idx >> 3, col = (idx & 7) * 8;
            cpa16(fsh + row * QP + col, Qg + (size_t)row * 3 * NE + col, true);
        }
        asm volatile("cp.async.commit_group;");
        asm volatile("cp.async.wait_group 0;");
        __syncthreads();
    }

    unsigned qf[4][4];
#pragma unroll
    for (int ks = 0; ks < 4; ks++) {
        const __half* p = &fsh[wrow * QP + ks * 16 + 2 * lc];
        qf[ks][0] = lds_u32(p);
        qf[ks][1] = lds_u32(p + 8 * QP);
        qf[ks][2] = lds_u32(p + 8);
        qf[ks][3] = lds_u32(p + 8 * QP + 8);
    }
    __syncthreads();

    float oacc[8][4];
#pragma unroll
    for (int j = 0; j < 8; j++)
#pragma unroll
        for (int q = 0; q < 4; q++) oacc[j][q] = 0.f;
    float m0 = -1e30f, m1 = -1e30f, l0 = 0.f, l1 = 0.f;

    const int row0 = qt * 128 + wrow;
    const int row1 = row0 + 8;
    const int ntiles = 2 * qt + 2;
    const int sp  = tid >> 3;           // V: seq-pair index
    const int hd0 = (tid & 7) * 8;      // V: head-dim offset

    // K-load slots (2 x 16B chunks per thread)
    const int kr0 = tid >> 3,           kc0 = (tid & 7) * 8;
    const int kr1 = (tid + 256) >> 3,   kc1 = ((tid + 256) & 7) * 8;

    // ---- prologue: tile 0 ----
    {
        const __half* Kg = base + NE;
        cpa16(sK + kr0 * QP + kc0, Kg + (size_t)kr0 * 3 * NE + kc0, true);
        cpa16(sK + kr1 * QP + kc1, Kg + (size_t)kr1 * 3 * NE + kc1, true);
        asm volatile("cp.async.commit_group;");
        const __half* v0 = base + 2 * NE + (size_t)(2 * sp) * 3 * NE + hd0;
        uint4 u0 = *(const uint4*)v0;
        uint4 u1 = *(const uint4*)(v0 + 3 * NE);
        asm volatile("cp.async.wait_group 0;");
        __half ha[8], hbv[8];
        *(uint4*)ha = u0; *(uint4*)hbv = u1;
#pragma unroll
        for (int q = 0; q < 8; q++)
            *(__half2*)&sVt[(hd0 + q) * VP + 2 * sp] = __halves2half2(ha[q], hbv[q]);
        __syncthreads();
    }

    for (int j = 0; j < ntiles; j++) {
        const int buf = j & 1, nxt = buf ^ 1;
        const bool more = (j + 1 < ntiles);
        uint4 u0, u1;

        // prefetch tile j+1: K via cp.async, V into registers
        if (more) {
            const __half* Kg = base + NE + (size_t)((j + 1) * 64) * 3 * NE;
            __half* dK = sK + nxt * KBUF;
            cpa16(dK + kr0 * QP + kc0, Kg + (size_t)kr0 * 3 * NE + kc0, true);
            cpa16(dK + kr1 * QP + kc1, Kg + (size_t)kr1 * 3 * NE + kc1, true);
            const __half* v0 = base + 2 * NE
                             + (size_t)((j + 1) * 64 + 2 * sp) * 3 * NE + hd0;
            u0 = *(const uint4*)v0;
            u1 = *(const uint4*)(v0 + 3 * NE);
        }
        asm volatile("cp.async.commit_group;");

        const __half* Kb = sK + buf * KBUF;
        const __half* Vb = sVt + buf * VBUF;

        // ---- S = Q K^T ----
        float sacc[8][4];
#pragma unroll
        for (int jn = 0; jn < 8; jn++)
#pragma unroll
            for (int q = 0; q < 4; q++) sacc[jn][q] = 0.f;
#pragma unroll
        for (int ks = 0; ks < 4; ks++) {
            const int k0 = ks * 16 + 2 * lc;
#pragma unroll
            for (int jn = 0; jn < 8; jn++) {
                unsigned bf[2];
                const __half* p = &Kb[(jn * 8 + lr) * QP + k0];
                bf[0] = lds_u32(p);
                bf[1] = lds_u32(p + 8);
                mma16(sacc[jn], qf[ks], bf);
            }
        }

        // ---- mask + scale + tile max ----
        const float sc = 0.125f;
        float tm0 = -1e30f, tm1 = -1e30f;
#pragma unroll
        for (int jn = 0; jn < 8; jn++) {
            int col = j * 64 + jn * 8 + (lc << 1);
            sacc[jn][0] = (col     <= row0) ? sacc[jn][0] * sc : -1e30f;
            sacc[jn][1] = (col + 1 <= row0) ? sacc[jn][1] * sc : -1e30f;
            sacc[jn][2] = (col     <= row1) ? sacc[jn][2] * sc : -1e30f;
            sacc[jn][3] = (col + 1 <= row1) ? sacc[jn][3] * sc : -1e30f;
            tm0 = fmaxf(tm0, fmaxf(sacc[jn][0], sacc[jn][1]));
            tm1 = fmaxf(tm1, fmaxf(sacc[jn][2], sacc[jn][3]));
        }
        tm0 = fmaxf(tm0, __shfl_xor_sync(0xffffffffu, tm0, 1));
        tm0 = fmaxf(tm0, __shfl_xor_sync(0xffffffffu, tm0, 2));
        tm1 = fmaxf(tm1, __shfl_xor_sync(0xffffffffu, tm1, 1));
        tm1 = fmaxf(tm1, __shfl_xor_sync(0xffffffffu, tm1, 2));

        float mn0 = fmaxf(m0, tm0), mn1 = fmaxf(m1, tm1);
        float a0 = __expf(m0 - mn0), a1 = __expf(m1 - mn1);
        m0 = mn0; m1 = mn1;

        float rs0 = 0.f, rs1 = 0.f;
#pragma unroll
        for (int jn = 0; jn < 8; jn++) {
            sacc[jn][0] = __expf(sacc[jn][0] - m0);
            sacc[jn][1] = __expf(sacc[jn][1] - m0);
            sacc[jn][2] = __expf(sacc[jn][2] - m1);
            sacc[jn][3] = __expf(sacc[jn][3] - m1);
            rs0 += sacc[jn][0] + sacc[jn][1];
            rs1 += sacc[jn][2] + sacc[jn][3];
        }
        rs0 += __shfl_xor_sync(0xffffffffu, rs0, 1);
        rs0 += __shfl_xor_sync(0xffffffffu, rs0, 2);
        rs1 += __shfl_xor_sync(0xffffffffu, rs1, 1);
        rs1 += __shfl_xor_sync(0xffffffffu, rs1, 2);
        l0 = l0 * a0 + rs0;
        l1 = l1 * a1 + rs1;
#pragma unroll
        for (int jo = 0; jo < 8; jo++) {
            oacc[jo][0] *= a0; oacc[jo][1] *= a0;
            oacc[jo][2] *= a1; oacc[jo][3] *= a1;
        }

        // ---- O += P V ----
#pragma unroll
        for (int ks = 0; ks < 4; ks++) {
            unsigned af[4];
            {
                __half2 t;
                t = __floats2half2_rn(sacc[2 * ks][0],     sacc[2 * ks][1]);     af[0] = *(unsigned*)&t;
                t = __floats2half2_rn(sacc[2 * ks][2],     sacc[2 * ks][3]);     af[1] = *(unsigned*)&t;
                t = __floats2half2_rn(sacc[2 * ks + 1][0], sacc[2 * ks + 1][1]); af[2] = *(unsigned*)&t;
                t = __floats2half2_rn(sacc[2 * ks + 1][2], sacc[2 * ks + 1][3]); af[3] = *(unsigned*)&t;
            }
            const int k0 = ks * 16 + 2 * lc;
#pragma unroll
            for (int jo = 0; jo < 8; jo++) {
                unsigned bf[2];
                const __half* p = &Vb[(jo * 8 + lr) * VP + k0];
                bf[0] = lds_u32(p);
                bf[1] = lds_u32(p + 8);
                mma16(oacc[jo], af, bf);
            }
        }
        __syncthreads();   // all warps done reading buf

        if (more) {
            asm volatile("cp.async.wait_group 0;");   // K(j+1) arrived (overlapped)
            __half ha[8], hbv[8];
            *(uint4*)ha = u0; *(uint4*)hbv = u1;
            __half* dV = sVt + nxt * VBUF;
#pragma unroll
            for (int q = 0; q < 8; q++)
                *(__half2*)&dV[(hd0 + q) * VP + 2 * sp] = __halves2half2(ha[q], hbv[q]);
        }
        __syncthreads();   // V(j+1) visible to all warps
    }

    // ---- finalize ----
    float inv0 = 1.0f / l0, inv1 = 1.0f / l1;
    __half* y0 = g_y + ((size_t)b * NT + row0) * NE + h * 64;
    __half* y1 = y0 + (size_t)8 * NE;
#pragma unroll
    for (int jo = 0; jo < 8; jo++) {
        int col = jo * 8 + (lc << 1);
        *(__half2*)&y0[col] = __floats2half2_rn(oacc[jo][0] * inv0, oacc[jo][1] * inv0);
        *(__half2*)&y1[col] = __floats2half2_rn(oacc[jo][2] * inv1, oacc[jo][3] * inv1);
    }
}

// ------------------------------- loss ---------------------------------------
__global__ void loss_lse_kernel(const float* __restrict__ logits,
                                const int* __restrict__ targets) {
    int r = blockIdx.x * 128 + threadIdx.x;
    if (r >= NM) return;
    const float* L = g_att + (size_t)r * LSE_STRIDE;
    float m = -1e30f, s = 0.f;
    for (int k = 0; k < NBLK64; k++) {
        float m2 = L[2 * k], s2 = L[2 * k + 1];
        float M = fmaxf(m, m2);
        s = s * __expf(m - M) + s2 * __expf(m2 - M);
        m = M;
    }
    int tgt = targets[r];
    float nll = 0.f;
    if (tgt != -1) nll = m + logf(s) - logits[(size_t)r * NV + tgt];
    g_nll[r] = nll;
}

__global__ void loss_row_kernel(const float* __restrict__ logits,
                                const int* __restrict__ targets,
                                int row0, int ldl) {
    int r = blockIdx.x;
    int tid = threadIdx.x;
    const float* L = logits + (size_t)r * ldl;
    float m = -1e30f, sacc = 0.f;
    for (int j = tid; j < NV; j += 256) {
        float v = L[j];
        if (v > m) { sacc = sacc * expf(m - v) + 1.0f; m = v; }
        else       { sacc += expf(v - m); }
    }
    __shared__ float sm[256], ss[256];
    sm[tid] = m; ss[tid] = sacc; __syncthreads();
    for (int o = 128; o > 0; o >>= 1) {
        if (tid < o) {
            float m2 = sm[tid + o], s2 = ss[tid + o];
            float M  = fmaxf(sm[tid], m2);
            ss[tid]  = ss[tid] * expf(sm[tid] - M) + s2 * expf(m2 - M);
            sm[tid]  = M;
        }
        __syncthreads();
    }
    if (tid == 0) {
        int grow = row0 + r;
        int tgt = targets[grow];
        float nll = 0.f;
        if (tgt != -1) nll = sm[0] + logf(ss[0]) - L[tgt];
        g_nll[grow] = nll;
    }
}

__global__ void loss_reduce_kernel(const int* __restrict__ targets,
                                   float* __restrict__ out) {
    int tid = threadIdx.x;
    __shared__ float ssum[256];
    __shared__ int scnt[256];
    float s = 0.f; int c = 0;
    for (int r = tid; r < NM; r += 256)
        if (targets[r] != -1) { s += g_nll[r]; c++; }
    ssum[tid] = s; scnt[tid] = c; __syncthreads();
    for (int o = 128; o > 0; o >>= 1) {
        if (tid < o) { ssum[tid] += ssum[tid + o]; scnt[tid] += scnt[tid + o]; }
        __syncthreads();
    }
    if (tid == 0) out[0] = ssum[0] / (float)max(scnt[0], 1);
}

// ------------------------------- host ---------------------------------------
static const int MMA_SMEM = 2 * STG_H * (int)sizeof(__half);   // 73728 B

template <int EPI>
static void launch_mma(const __half* A, const __half* B, void* C,
                       int M, int N, int K, int lda, int ldb, int ldc) {
    dim3 grid((N + 127) / 128, M / 128);
    mma_gemm<EPI, 0><<<grid, 128, MMA_SMEM>>>(A, B, C, M, N, K, lda, ldb, ldc);
}

static void conv_f2h(const float* s, __half* d, size_t n) {
    int n4 = (int)(n / 4);
    f2h_kernel<<<(n4 + 255) / 256, 256>>>((const float4*)s, (__half2*)d, n4);
}

extern "C" void kernel_launch(void* const* d_in, const int* in_sizes, int n_in,
                              void* d_out, int out_size) {
    const int*   idx      = (const int*)  d_in[0];
    const int*   targets  = (const int*)  d_in[1];
    const float* wte      = (const float*)d_in[2];
    const float* wpe      = (const float*)d_in[3];
    const float* ln1_w    = (const float*)d_in[4];
    const float* ln1_b    = (const float*)d_in[5];
    const float* attn_w   = (const float*)d_in[6];
    const float* attn_pw  = (const float*)d_in[7];
    const float* ln2_w    = (const float*)d_in[8];
    const float* ln2_b    = (const float*)d_in[9];
    const float* fc_w     = (const float*)d_in[10];
    const float* fc_pw    = (const float*)d_in[11];
    const float* lnf_w    = (const float*)d_in[12];
    const float* lnf_b    = (const float*)d_in[13];
    const float* lm_w     = (const float*)d_in[14];

    cudaFuncSetAttribute((void*)mma_gemm<0, 0>, cudaFuncAttributeMaxDynamicSharedMemorySize, MMA_SMEM);
    cudaFuncSetAttribute((void*)mma_gemm<1, 0>, cudaFuncAttributeMaxDynamicSharedMemorySize, MMA_SMEM);
    cudaFuncSetAttribute((void*)mma_gemm<2, 0>, cudaFuncAttributeMaxDynamicSharedMemorySize, MMA_SMEM);
    cudaFuncSetAttribute((void*)mma_gemm<3, 0>, cudaFuncAttributeMaxDynamicSharedMemorySize, MMA_SMEM);
    cudaFuncSetAttribute((void*)mma_gemm<4, 1>, cudaFuncAttributeMaxDynamicSharedMemorySize, MMA_SMEM);
    cudaFuncSetAttribute((void*)flash_attn_kernel, cudaFuncAttributeMaxDynamicSharedMemorySize, FA_SMEM);

    float *x, *att;
    __half *h, *qkv, *y, *fc;
    __half *wa, *wp, *wf, *wfp, *wl;
    cudaGetSymbolAddress((void**)&x,   g_x);
    cudaGetSymbolAddress((void**)&h,   g_h);
    cudaGetSymbolAddress((void**)&qkv, g_qkv);
    cudaGetSymbolAddress((void**)&y,   g_y);
    cudaGetSymbolAddress((void**)&fc,  g_fc);
    cudaGetSymbolAddress((void**)&att, g_att);
    cudaGetSymbolAddress((void**)&wa,  w_attn);
    cudaGetSymbolAddress((void**)&wp,  w_proj);
    cudaGetSymbolAddress((void**)&wf,  w_fc);
    cudaGetSymbolAddress((void**)&wfp, w_fcp);
    cudaGetSymbolAddress((void**)&wl,  w_lm);

    conv_f2h(attn_w,  wa,  (size_t)NLAYER * 3 * NE * NE);
    conv_f2h(attn_pw, wp,  (size_t)NLAYER * NE * NE);
    conv_f2h(fc_w,    wf,  (size_t)NLAYER * 4 * NE * NE);
    conv_f2h(fc_pw,   wfp, (size_t)NLAYER * NE * 4 * NE);
    conv_f2h(lm_w,    wl,  (size_t)NV * NE);

    embed_kernel<<<NM, 256>>>(idx, wte, wpe);

    for (int i = 0; i < NLAYER; i++) {
        const __half* aw  = wa  + (size_t)i * 3 * NE * NE;
        const __half* pw  = wp  + (size_t)i * NE * NE;
        const __half* fw  = wf  + (size_t)i * 4 * NE * NE;
        const __half* fpw = wfp + (size_t)i * NE * 4 * NE;

        ln_kernel<<<NM, 256>>>(x, ln1_w + i * NE, ln1_b + i * NE, h);
        launch_mma<1>(h, aw, qkv, NM, 3 * NE, NE, NE, NE, 3 * NE);
        flash_attn_kernel<<<dim3(NT / 128, NB * NH), 256, FA_SMEM>>>();
        launch_mma<3>(y, pw, x, NM, NE, NE, NE, NE, NE);
        ln_kernel<<<NM, 256>>>(x, ln2_w + i * NE, ln2_b + i * NE, h);
        launch_mma<2>(h, fw, fc, NM, 4 * NE, NE, NE, NE, 4 * NE);
        launch_mma<3>(fc, fpw, x, NM, NE, 4 * NE, 4 * NE, 4 * NE, NE);
    }

    ln_kernel<<<NM, 256>>>(x, lnf_w, lnf_b, h);

    const size_t P = (size_t)NM * NV;
    float* out = (float*)d_out;

    if ((size_t)out_size >= P) {
        dim3 grid(NM / 128, (NV + 127) / 128);
        mma_gemm<4, 1><<<grid, 128, MMA_SMEM>>>(h, wl, out, NM, NV, NE, NE, NE, NV);
        loss_lse_kernel<<<NM / 128, 128>>>(out, targets);
        if ((size_t)out_size >= P + 1)
            loss_reduce_kernel<<<1, 256>>>(targets, out + P);
    } else {
        const int CHUNK = 1024;
        for (int c = 0; c < NM / CHUNK; c++) {
            launch_mma<0>(h + (size_t)c * CHUNK * NE, wl, att,
                          CHUNK, NV, NE, NE, NE, NV);
            loss_row_kernel<<<CHUNK, 256>>>(att, targets, c * CHUNK, NV);
        }
        int li = (out_size >= 1) ? out_size - 1 : 0;
        loss_reduce_kernel<<<1, 256>>>(targets, out + li);
    }
}

// round 17
// speedup vs baseline: 1.1226x; 1.1226x over previous
#include <cuda_runtime.h>
#include <cuda_fp16.h>
#include <math.h>

// ---------------------------------------------------------------------------
// NanoGPT forward (B=4, T=1024, E=1024, H=16, L=6, V=50257)
// R16: dense GEMM with XOR-swizzled smem (no padding), 3-stage pipeline,
//      ONE barrier per k-iteration, 96KB/CTA -> 2 CTAs/SM kept.
//      Flash attention / LN / f2h / loss = R13 exact (known 4577us).
// ---------------------------------------------------------------------------

#define NB     4
#define NT     1024
#define NE     1024
#define NH     16
#define HDIM   64
#define NLAYER 6
#define NV     50257
#define NM     (NB * NT)
#define NBLK64 786                  // ceil(NV/64)
#define LSE_STRIDE 1600
#define LN_EPS 1e-5f

// ------------------------------- scratch -----------------------------------
__device__ float  g_x  [NM * NE];
__device__ __half g_h  [NM * NE];
__device__ __half g_qkv[NM * 3 * NE];
__device__ __half g_y  [NM * NE];
__device__ __half g_fc [NM * 4 * NE];
__device__ float  g_att[(size_t)1024 * NV];        // logits chunk / lse scratch
__device__ float  g_nll[NM];

__device__ __half w_attn[(size_t)NLAYER * 3 * NE * NE];
__device__ __half w_proj[(size_t)NLAYER * NE * NE];
__device__ __half w_fc  [(size_t)NLAYER * 4 * NE * NE];
__device__ __half w_fcp [(size_t)NLAYER * NE * 4 * NE];
__device__ __half w_lm  [(size_t)NV * NE];

// ----------------------------- helpers --------------------------------------
__device__ __forceinline__ void mma16(float* c, const unsigned* a, const unsigned* b) {
    asm volatile(
        "mma.sync.aligned.m16n8k16.row.col.f32.f16.f16.f32 "
        "{%0,%1,%2,%3}, {%4,%5,%6,%7}, {%8,%9}, {%0,%1,%2,%3};"
        : "+f"(c[0]), "+f"(c[1]), "+f"(c[2]), "+f"(c[3])
        : "r"(a[0]), "r"(a[1]), "r"(a[2]), "r"(a[3]), "r"(b[0]), "r"(b[1]));
}

__device__ __forceinline__ void cpa16(void* dst, const void* src, bool full) {
    unsigned d = (unsigned)__cvta_generic_to_shared(dst);
    int sz = full ? 16 : 0;
    asm volatile("cp.async.cg.shared.global [%0], [%1], 16, %2;"
                 :: "r"(d), "l"(src), "r"(sz));
}

__device__ __forceinline__ unsigned lds_u32(const __half* p) {
    return *(const unsigned*)p;
}

__device__ __forceinline__ float gelu_f(float x) {
    return 0.5f * x * (1.0f + erff(x * 0.70710678118654752f));
}

// --------------------------- f32 -> f16 convert ------------------------------
__global__ void f2h_kernel(const float4* __restrict__ src,
                           __half2* __restrict__ dst, int n4) {
    int i = blockIdx.x * blockDim.x + threadIdx.x;
    if (i < n4) {
        float4 v = src[i];
        dst[2 * i]     = __floats2half2_rn(v.x, v.y);
        dst[2 * i + 1] = __floats2half2_rn(v.z, v.w);
    }
}

// ------------------------------- embed -------------------------------------
__global__ void embed_kernel(const int* __restrict__ idx,
                             const float* __restrict__ wte,
                             const float* __restrict__ wpe) {
    int row = blockIdx.x;
    int t   = row % NT;
    int tok = idx[row];
    const float* s = wte + (size_t)tok * NE;
    const float* p = wpe + (size_t)t * NE;
    float* o = g_x + (size_t)row * NE;
    for (int c = threadIdx.x; c < NE; c += blockDim.x)
        o[c] = s[c] + p[c];
}

// ------------------------------ layernorm -----------------------------------
__global__ void ln_kernel(const float* __restrict__ in,
                          const float* __restrict__ w,
                          const float* __restrict__ b,
                          __half* __restrict__ out) {
    int row = blockIdx.x;
    int tid = threadIdx.x;
    const float* x = in + (size_t)row * NE;
    __half* o = out + (size_t)row * NE;

    float4 v = *(const float4*)(x + tid * 4);
    float s  = v.x + v.y + v.z + v.w;
    float s2 = v.x * v.x + v.y * v.y + v.z * v.z + v.w * v.w;

#pragma unroll
    for (int d = 16; d > 0; d >>= 1) {
        s  += __shfl_xor_sync(0xffffffffu, s,  d);
        s2 += __shfl_xor_sync(0xffffffffu, s2, d);
    }

    __shared__ float ws[8], ws2[8];
    __shared__ float s_mu, s_rstd;
    int wid = tid >> 5, lane = tid & 31;
    if (lane == 0) { ws[wid] = s; ws2[wid] = s2; }
    __syncthreads();
    if (tid == 0) {
        float ts = 0.f, ts2 = 0.f;
#pragma unroll
        for (int k = 0; k < 8; k++) { ts += ws[k]; ts2 += ws2[k]; }
        float mu  = ts * (1.0f / NE);
        float var = ts2 * (1.0f / NE) - mu * mu;
        s_mu   = mu;
        s_rstd = rsqrtf(var + LN_EPS);
    }
    __syncthreads();
    float mu = s_mu, rstd = s_rstd;

    const float4 wv = *(const float4*)(w + tid * 4);
    const float4 bv = *(const float4*)(b + tid * 4);
    __half2 h0 = __floats2half2_rn((v.x - mu) * rstd * wv.x + bv.x,
                                   (v.y - mu) * rstd * wv.y + bv.y);
    __half2 h1 = __floats2half2_rn((v.z - mu) * rstd * wv.z + bv.z,
                                   (v.w - mu) * rstd * wv.w + bv.w);
    *(__half2*)(o + tid * 4)     = h0;
    *(__half2*)(o + tid * 4 + 2) = h1;
}

// ------------------------- fp16 tensor-core GEMM -----------------------------
// C[M,N] = A[M,K] * B^T. Block 128x128, BK=64, 3-stage pipeline, XOR-swizzled
// smem (no padding; chunk16 ^= row&7), ONE barrier per k-iteration.
// 128 threads = 4 warps (2x2), warp tile 64x64, 2 CTAs/SM (96KB smem).
// EPI: 0 f32 store (guarded), 1 f16 store, 2 gelu->f16, 3 f32 +=,
//      4 f32 store (guarded) + per-(row, 64-col block) logsumexp into g_att
// RAST: 0 grid=(N/128, M/128); 1 swapped. Requires K % 64 == 0.
#define STG3_H (2 * 128 * 64)             // halves per stage: A[128][64]+B[128][64]

template <int EPI, int RAST>
__global__ void __launch_bounds__(128, 2)
mma_gemm(const __half* __restrict__ A, const __half* __restrict__ B,
         void* __restrict__ Cv,
         int M, int N, int K, int lda, int ldb, int ldc) {
    extern __shared__ __half sh[];
    const int bxn  = RAST ? blockIdx.y : blockIdx.x;
    const int bxm  = RAST ? blockIdx.x : blockIdx.y;
    const int bm   = bxm * 128;
    const int bn   = bxn * 128;
    const int tid  = threadIdx.x;
    const int lane = tid & 31;
    const int wid  = tid >> 5;
    const int wm   = (wid >> 1) * 64;
    const int wn   = (wid & 1) * 64;
    const int lr   = lane >> 2;           // 0..7 == fragment row & 7
    const int lc   = lane & 3;

    // staging: 8 chunks (16B) each for A and B; dst chunk XOR-swizzled by row&7
    const __half* Asrc[8];
    const __half* Bsrc[8];
    bool bval[8];
    int  dOff[8];
#pragma unroll
    for (int i = 0; i < 8; i++) {
        int c = tid + i * 128;
        int row = c >> 3, ch = c & 7;
        dOff[i] = row * 64 + (ch ^ (row & 7)) * 8;
        Asrc[i] = A + (size_t)(bm + row) * lda + ch * 8;
        bval[i] = (bn + row) < N;
        Bsrc[i] = B + (size_t)min(bn + row, N - 1) * ldb + ch * 8;
    }

    float acc[4][8][4];
#pragma unroll
    for (int i = 0; i < 4; i++)
#pragma unroll
        for (int j = 0; j < 8; j++)
#pragma unroll
            for (int q = 0; q < 4; q++) acc[i][j][q] = 0.f;

    const int KT = K >> 6;

    // prologue: stage tiles 0 and 1 (separate commit groups)
#pragma unroll
    for (int s = 0; s < 2; s++) {
        __half* sA = sh + s * STG3_H;
        __half* sB = sA + 128 * 64;
        int k0 = s * 64;
#pragma unroll
        for (int i = 0; i < 8; i++) {
            cpa16(sA + dOff[i], Asrc[i] + k0, true);
            cpa16(sB + dOff[i], Bsrc[i] + k0, bval[i]);
        }
        asm volatile("cp.async.commit_group;");
    }

    for (int kt = 0; kt < KT; kt++) {
        asm volatile("cp.async.wait_group 1;");  // tile kt complete
        __syncthreads();                          // publish kt; retire readers of buf (kt+2)%3

        // prefetch tile kt+2 into buffer (kt+2)%3 (last computed at iter kt-1)
        int pf = kt + 2;
        if (pf < KT) {
            __half* sA = sh + (pf % 3) * STG3_H;
            __half* sB = sA + 128 * 64;
            int k0 = pf * 64;
#pragma unroll
            for (int i = 0; i < 8; i++) {
                cpa16(sA + dOff[i], Asrc[i] + k0, true);
                cpa16(sB + dOff[i], Bsrc[i] + k0, bval[i]);
            }
        }
        asm volatile("cp.async.commit_group;");   // uniform group count

        const __half* As = sh + (kt % 3) * STG3_H;
        const __half* Bs = As + 128 * 64;
#pragma unroll
        for (int ks = 0; ks < 4; ks++) {
            const int c8a = (2 * ks)     ^ lr;    // swizzled chunk for k0..k0+7
            const int c8b = (2 * ks + 1) ^ lr;    // swizzled chunk for k0+8..k0+15
            const int o_a = c8a * 8 + 2 * lc;
            const int o_b = c8b * 8 + 2 * lc;
            unsigned afr[4][4], bfr[8][2];
#pragma unroll
            for (int i = 0; i < 4; i++) {
                const __half* p = &As[(wm + i * 16 + lr) * 64];
                afr[i][0] = lds_u32(p + o_a);
                afr[i][1] = lds_u32(p + 8 * 64 + o_a);
                afr[i][2] = lds_u32(p + o_b);
                afr[i][3] = lds_u32(p + 8 * 64 + o_b);
            }
#pragma unroll
            for (int j = 0; j < 8; j++) {
                const __half* p = &Bs[(wn + j * 8 + lr) * 64];
                bfr[j][0] = lds_u32(p + o_a);
                bfr[j][1] = lds_u32(p + o_b);
            }
#pragma unroll
            for (int i = 0; i < 4; i++)
#pragma unroll
                for (int j = 0; j < 8; j++)
                    mma16(acc[i][j], afr[i], bfr[j]);
        }
    }

    // ---- epilogue ----
#pragma unroll
    for (int i = 0; i < 4; i++) {
        int r0 = bm + wm + i * 16 + lr;
#pragma unroll
        for (int j = 0; j < 8; j++) {
            int c0 = bn + wn + j * 8 + (lc << 1);
            const float* a4 = acc[i][j];
            if (EPI == 0 || EPI == 4) {
                float* C0 = (float*)Cv + (size_t)r0 * ldc;
                float* C1 = C0 + (size_t)8 * ldc;
#pragma unroll
                for (int q = 0; q < 2; q++) {
                    int col = c0 + q;
                    if (col < N) { C0[col] = a4[q]; C1[col] = a4[q + 2]; }
                }
            } else if (EPI == 1) {
                __half* C0 = (__half*)Cv + (size_t)r0 * ldc;
                __half* C1 = C0 + (size_t)8 * ldc;
                *(__half2*)&C0[c0] = __floats2half2_rn(a4[0], a4[1]);
                *(__half2*)&C1[c0] = __floats2half2_rn(a4[2], a4[3]);
            } else if (EPI == 2) {
                __half* C0 = (__half*)Cv + (size_t)r0 * ldc;
                __half* C1 = C0 + (size_t)8 * ldc;
                *(__half2*)&C0[c0] = __floats2half2_rn(gelu_f(a4[0]), gelu_f(a4[1]));
                *(__half2*)&C1[c0] = __floats2half2_rn(gelu_f(a4[2]), gelu_f(a4[3]));
            } else if (EPI == 3) {
                float* C0 = (float*)Cv + (size_t)r0 * ldc;
                float* C1 = C0 + (size_t)8 * ldc;
                C0[c0] += a4[0]; C0[c0 + 1] += a4[1];
                C1[c0] += a4[2]; C1[c0 + 1] += a4[3];
            }
        }
    }

    if (EPI == 4) {
        int blk = (bn + wn) >> 6;
#pragma unroll
        for (int i = 0; i < 4; i++) {
#pragma unroll
            for (int hh = 0; hh < 2; hh++) {
                float lm_ = -1e30f;
#pragma unroll
                for (int j = 0; j < 8; j++) {
                    int c0 = bn + wn + j * 8 + (lc << 1);
                    float v0 = (c0     < N) ? acc[i][j][hh * 2]     : -1e30f;
                    float v1 = (c0 + 1 < N) ? acc[i][j][hh * 2 + 1] : -1e30f;
                    lm_ = fmaxf(lm_, fmaxf(v0, v1));
                }
                lm_ = fmaxf(lm_, __shfl_xor_sync(0xffffffffu, lm_, 1));
                lm_ = fmaxf(lm_, __shfl_xor_sync(0xffffffffu, lm_, 2));
                float ls = 0.f;
#pragma unroll
                for (int j = 0; j < 8; j++) {
                    int c0 = bn + wn + j * 8 + (lc << 1);
                    if (c0     < N) ls += __expf(acc[i][j][hh * 2]     - lm_);
                    if (c0 + 1 < N) ls += __expf(acc[i][j][hh * 2 + 1] - lm_);
                }
                ls += __shfl_xor_sync(0xffffffffu, ls, 1);
                ls += __shfl_xor_sync(0xffffffffu, ls, 2);
                if (lc == 0) {
                    int row = bm + wm + i * 16 + lr + hh * 8;
                    float* lse = g_att + (size_t)row * LSE_STRIDE + blk * 2;
                    lse[0] = lm_;
                    lse[1] = ls;
                }
            }
        }
    }
}

// --------------------------- flash attention ---------------------------------
// (exact R13 version — known good, 4577us configuration)
#define QP 72
#define VP 74
#define FA_SMEM ((64 * QP + 64 * VP) * (int)sizeof(__half))

__global__ void __launch_bounds__(256, 2)
flash_attn_kernel() {
    extern __shared__ __half fsh[];
    __half* sK  = fsh;                  // [64][QP]
    __half* sVt = fsh + 64 * QP;        // [64 hd][VP seq]

    const int qt  = blockIdx.x;
    const int bh  = blockIdx.y;
    const int b   = bh >> 4, h = bh & 15;
    const int tid = threadIdx.x;
    const int w   = tid >> 5;
    const int lane = tid & 31;
    const int lr  = lane >> 2;
    const int lc  = lane & 3;
    const int wrow = w * 16 + lr;

    const __half* base = g_qkv + (size_t)b * NT * 3 * NE + h * 64;

    {
        const __half* Qg = base + (size_t)(qt * 128) * 3 * NE;
#pragma unroll
        for (int i = 0; i < 4; i++) {
            int idx = tid + i * 256;
            int row = idx >> 3, col = (idx & 7) * 8;
            cpa16(fsh + row * QP + col, Qg + (size_t)row * 3 * NE + col, true);
        }
        asm volatile("cp.async.commit_group;");
        asm volatile("cp.async.wait_group 0;");
        __syncthreads();
    }

    unsigned qf[4][4];
#pragma unroll
    for (int ks = 0; ks < 4; ks++) {
        const __half* p = &fsh[wrow * QP + ks * 16 + 2 * lc];
        qf[ks][0] = lds_u32(p);
        qf[ks][1] = lds_u32(p + 8 * QP);
        qf[ks][2] = lds_u32(p + 8);
        qf[ks][3] = lds_u32(p + 8 * QP + 8);
    }
    __syncthreads();

    float oacc[8][4];
#pragma unroll
    for (int j = 0; j < 8; j++)
#pragma unroll
        for (int q = 0; q < 4; q++) oacc[j][q] = 0.f;
    float m0 = -1e30f, m1 = -1e30f, l0 = 0.f, l1 = 0.f;

    const int row0 = qt * 128 + wrow;
    const int row1 = row0 + 8;
    const int ntiles = 2 * qt + 2;
    const int sp  = tid >> 3;
    const int hd0 = (tid & 7) * 8;

    for (int j = 0; j < ntiles; j++) {
        const __half* Kg = base + NE + (size_t)(j * 64) * 3 * NE;
#pragma unroll
        for (int i = 0; i < 2; i++) {
            int idx = tid + i * 256;
            int row = idx >> 3, col = (idx & 7) * 8;
            cpa16(sK + row * QP + col, Kg + (size_t)row * 3 * NE + col, true);
        }
        asm volatile("cp.async.commit_group;");
        {
            const __half* v0 = base + 2 * NE + (size_t)(j * 64 + 2 * sp) * 3 * NE + hd0;
            const __half* v1 = v0 + 3 * NE;
            uint4 u0 = *(const uint4*)v0;
            uint4 u1 = *(const uint4*)v1;
            __half ha[8], hbv[8];
            *(uint4*)ha = u0; *(uint4*)hbv = u1;
#pragma unroll
            for (int q = 0; q < 8; q++)
                *(__half2*)&sVt[(hd0 + q) * VP + 2 * sp] = __halves2half2(ha[q], hbv[q]);
        }
        asm volatile("cp.async.wait_group 0;");
        __syncthreads();

        float sacc[8][4];
#pragma unroll
        for (int jn = 0; jn < 8; jn++)
#pragma unroll
            for (int q = 0; q < 4; q++) sacc[jn][q] = 0.f;
#pragma unroll
        for (int ks = 0; ks < 4; ks++) {
            const int k0 = ks * 16 + 2 * lc;
#pragma unroll
            for (int jn = 0; jn < 8; jn++) {
                unsigned bf[2];
                const __half* p = &sK[(jn * 8 + lr) * QP + k0];
                bf[0] = lds_u32(p);
                bf[1] = lds_u32(p + 8);
                mma16(sacc[jn], qf[ks], bf);
            }
        }

        const float sc = 0.125f;
        float tm0 = -1e30f, tm1 = -1e30f;
#pragma unroll
        for (int jn = 0; jn < 8; jn++) {
            int col = j * 64 + jn * 8 + (lc << 1);
            sacc[jn][0] = (col     <= row0) ? sacc[jn][0] * sc : -1e30f;
            sacc[jn][1] = (col + 1 <= row0) ? sacc[jn][1] * sc : -1e30f;
            sacc[jn][2] = (col     <= row1) ? sacc[jn][2] * sc : -1e30f;
            sacc[jn][3] = (col + 1 <= row1) ? sacc[jn][3] * sc : -1e30f;
            tm0 = fmaxf(tm0, fmaxf(sacc[jn][0], sacc[jn][1]));
            tm1 = fmaxf(tm1, fmaxf(sacc[jn][2], sacc[jn][3]));
        }
        tm0 = fmaxf(tm0, __shfl_xor_sync(0xffffffffu, tm0, 1));
        tm0 = fmaxf(tm0, __shfl_xor_sync(0xffffffffu, tm0, 2));
        tm1 = fmaxf(tm1, __shfl_xor_sync(0xffffffffu, tm1, 1));
        tm1 = fmaxf(tm1, __shfl_xor_sync(0xffffffffu, tm1, 2));

        float mn0 = fmaxf(m0, tm0), mn1 = fmaxf(m1, tm1);
        float a0 = __expf(m0 - mn0), a1 = __expf(m1 - mn1);
        m0 = mn0; m1 = mn1;

        float rs0 = 0.f, rs1 = 0.f;
#pragma unroll
        for (int jn = 0; jn < 8; jn++) {
            sacc[jn][0] = __expf(sacc[jn][0] - m0);
            sacc[jn][1] = __expf(sacc[jn][1] - m0);
            sacc[jn][2] = __expf(sacc[jn][2] - m1);
            sacc[jn][3] = __expf(sacc[jn][3] - m1);
            rs0 += sacc[jn][0] + sacc[jn][1];
            rs1 += sacc[jn][2] + sacc[jn][3];
        }
        rs0 += __shfl_xor_sync(0xffffffffu, rs0, 1);
        rs0 += __shfl_xor_sync(0xffffffffu, rs0, 2);
        rs1 += __shfl_xor_sync(0xffffffffu, rs1, 1);
        rs1 += __shfl_xor_sync(0xffffffffu, rs1, 2);
        l0 = l0 * a0 + rs0;
        l1 = l1 * a1 + rs1;
#pragma unroll
        for (int jo = 0; jo < 8; jo++) {
            oacc[jo][0] *= a0; oacc[jo][1] *= a0;
            oacc[jo][2] *= a1; oacc[jo][3] *= a1;
        }

#pragma unroll
        for (int ks = 0; ks < 4; ks++) {
            unsigned af[4];
            {
                __half2 t;
                t = __floats2half2_rn(sacc[2 * ks][0],     sacc[2 * ks][1]);     af[0] = *(unsigned*)&t;
                t = __floats2half2_rn(sacc[2 * ks][2],     sacc[2 * ks][3]);     af[1] = *(unsigned*)&t;
                t = __floats2half2_rn(sacc[2 * ks + 1][0], sacc[2 * ks + 1][1]); af[2] = *(unsigned*)&t;
                t = __floats2half2_rn(sacc[2 * ks + 1][2], sacc[2 * ks + 1][3]); af[3] = *(unsigned*)&t;
            }
            const int k0 = ks * 16 + 2 * lc;
#pragma unroll
            for (int jo = 0; jo < 8; jo++) {
                unsigned bf[2];
                const __half* p = &sVt[(jo * 8 + lr) * VP + k0];
                bf[0] = lds_u32(p);
                bf[1] = lds_u32(p + 8);
                mma16(oacc[jo], af, bf);
            }
        }
        __syncthreads();
    }

    float inv0 = 1.0f / l0, inv1 = 1.0f / l1;
    __half* y0 = g_y + ((size_t)b * NT + row0) * NE + h * 64;
    __half* y1 = y0 + (size_t)8 * NE;
#pragma unroll
    for (int jo = 0; jo < 8; jo++) {
        int col = jo * 8 + (lc << 1);
        *(__half2*)&y0[col] = __floats2half2_rn(oacc[jo][0] * inv0, oacc[jo][1] * inv0);
        *(__half2*)&y1[col] = __floats2half2_rn(oacc[jo][2] * inv1, oacc[jo][3] * inv1);
    }
}

// ------------------------------- loss ---------------------------------------
__global__ void loss_lse_kernel(const float* __restrict__ logits,
                                const int* __restrict__ targets) {
    int r = blockIdx.x * 128 + threadIdx.x;
    if (r >= NM) return;
    const float* L = g_att + (size_t)r * LSE_STRIDE;
    float m = -1e30f, s = 0.f;
    for (int k = 0; k < NBLK64; k++) {
        float m2 = L[2 * k], s2 = L[2 * k + 1];
        float M = fmaxf(m, m2);
        s = s * __expf(m - M) + s2 * __expf(m2 - M);
        m = M;
    }
    int tgt = targets[r];
    float nll = 0.f;
    if (tgt != -1) nll = m + logf(s) - logits[(size_t)r * NV + tgt];
    g_nll[r] = nll;
}

__global__ void loss_row_kernel(const float* __restrict__ logits,
                                const int* __restrict__ targets,
                                int row0, int ldl) {
    int r = blockIdx.x;
    int tid = threadIdx.x;
    const float* L = logits + (size_t)r * ldl;
    float m = -1e30f, sacc = 0.f;
    for (int j = tid; j < NV; j += 256) {
        float v = L[j];
        if (v > m) { sacc = sacc * expf(m - v) + 1.0f; m = v; }
        else       { sacc += expf(v - m); }
    }
    __shared__ float sm[256], ss[256];
    sm[tid] = m; ss[tid] = sacc; __syncthreads();
    for (int o = 128; o > 0; o >>= 1) {
        if (tid < o) {
            float m2 = sm[tid + o], s2 = ss[tid + o];
            float M  = fmaxf(sm[tid], m2);
            ss[tid]  = ss[tid] * expf(sm[tid] - M) + s2 * expf(m2 - M);
            sm[tid]  = M;
        }
        __syncthreads();
    }
    if (tid == 0) {
        int grow = row0 + r;
        int tgt = targets[grow];
        float nll = 0.f;
        if (tgt != -1) nll = sm[0] + logf(ss[0]) - L[tgt];
        g_nll[grow] = nll;
    }
}

__global__ void loss_reduce_kernel(const int* __restrict__ targets,
                                   float* __restrict__ out) {
    int tid = threadIdx.x;
    __shared__ float ssum[256];
    __shared__ int scnt[256];
    float s = 0.f; int c = 0;
    for (int r = tid; r < NM; r += 256)
        if (targets[r] != -1) { s += g_nll[r]; c++; }
    ssum[tid] = s; scnt[tid] = c; __syncthreads();
    for (int o = 128; o > 0; o >>= 1) {
        if (tid < o) { ssum[tid] += ssum[tid + o]; scnt[tid] += scnt[tid + o]; }
        __syncthreads();
    }
    if (tid == 0) out[0] = ssum[0] / (float)max(scnt[0], 1);
}

// ------------------------------- host ---------------------------------------
static const int MMA_SMEM = 3 * STG3_H * (int)sizeof(__half);   // 98304 B

template <int EPI>
static void launch_mma(const __half* A, const __half* B, void* C,
                       int M, int N, int K, int lda, int ldb, int ldc) {
    dim3 grid((N + 127) / 128, M / 128);
    mma_gemm<EPI, 0><<<grid, 128, MMA_SMEM>>>(A, B, C, M, N, K, lda, ldb, ldc);
}

static void conv_f2h(const float* s, __half* d, size_t n) {
    int n4 = (int)(n / 4);
    f2h_kernel<<<(n4 + 255) / 256, 256>>>((const float4*)s, (__half2*)d, n4);
}

extern "C" void kernel_launch(void* const* d_in, const int* in_sizes, int n_in,
                              void* d_out, int out_size) {
    const int*   idx      = (const int*)  d_in[0];
    const int*   targets  = (const int*)  d_in[1];
    const float* wte      = (const float*)d_in[2];
    const float* wpe      = (const float*)d_in[3];
    const float* ln1_w    = (const float*)d_in[4];
    const float* ln1_b    = (const float*)d_in[5];
    const float* attn_w   = (const float*)d_in[6];
    const float* attn_pw  = (const float*)d_in[7];
    const float* ln2_w    = (const float*)d_in[8];
    const float* ln2_b    = (const float*)d_in[9];
    const float* fc_w     = (const float*)d_in[10];
    const float* fc_pw    = (const float*)d_in[11];
    const float* lnf_w    = (const float*)d_in[12];
    const float* lnf_b    = (const float*)d_in[13];
    const float* lm_w     = (const float*)d_in[14];

    cudaFuncSetAttribute((void*)mma_gemm<0, 0>, cudaFuncAttributeMaxDynamicSharedMemorySize, MMA_SMEM);
    cudaFuncSetAttribute((void*)mma_gemm<1, 0>, cudaFuncAttributeMaxDynamicSharedMemorySize, MMA_SMEM);
    cudaFuncSetAttribute((void*)mma_gemm<2, 0>, cudaFuncAttributeMaxDynamicSharedMemorySize, MMA_SMEM);
    cudaFuncSetAttribute((void*)mma_gemm<3, 0>, cudaFuncAttributeMaxDynamicSharedMemorySize, MMA_SMEM);
    cudaFuncSetAttribute((void*)mma_gemm<4, 1>, cudaFuncAttributeMaxDynamicSharedMemorySize, MMA_SMEM);
    cudaFuncSetAttribute((void*)flash_attn_kernel, cudaFuncAttributeMaxDynamicSharedMemorySize, FA_SMEM);

    float *x, *att;
    __half *h, *qkv, *y, *fc;
    __half *wa, *wp, *wf, *wfp, *wl;
    cudaGetSymbolAddress((void**)&x,   g_x);
    cudaGetSymbolAddress((void**)&h,   g_h);
    cudaGetSymbolAddress((void**)&qkv, g_qkv);
    cudaGetSymbolAddress((void**)&y,   g_y);
    cudaGetSymbolAddress((void**)&fc,  g_fc);
    cudaGetSymbolAddress((void**)&att, g_att);
    cudaGetSymbolAddress((void**)&wa,  w_attn);
    cudaGetSymbolAddress((void**)&wp,  w_proj);
    cudaGetSymbolAddress((void**)&wf,  w_fc);
    cudaGetSymbolAddress((void**)&wfp, w_fcp);
    cudaGetSymbolAddress((void**)&wl,  w_lm);

    conv_f2h(attn_w,  wa,  (size_t)NLAYER * 3 * NE * NE);
    conv_f2h(attn_pw, wp,  (size_t)NLAYER * NE * NE);
    conv_f2h(fc_w,    wf,  (size_t)NLAYER * 4 * NE * NE);
    conv_f2h(fc_pw,   wfp, (size_t)NLAYER * NE * 4 * NE);
    conv_f2h(lm_w,    wl,  (size_t)NV * NE);

    embed_kernel<<<NM, 256>>>(idx, wte, wpe);

    for (int i = 0; i < NLAYER; i++) {
        const __half* aw  = wa  + (size_t)i * 3 * NE * NE;
        const __half* pw  = wp  + (size_t)i * NE * NE;
        const __half* fw  = wf  + (size_t)i * 4 * NE * NE;
        const __half* fpw = wfp + (size_t)i * NE * 4 * NE;

        ln_kernel<<<NM, 256>>>(x, ln1_w + i * NE, ln1_b + i * NE, h);
        launch_mma<1>(h, aw, qkv, NM, 3 * NE, NE, NE, NE, 3 * NE);
        flash_attn_kernel<<<dim3(NT / 128, NB * NH), 256, FA_SMEM>>>();
        launch_mma<3>(y, pw, x, NM, NE, NE, NE, NE, NE);
        ln_kernel<<<NM, 256>>>(x, ln2_w + i * NE, ln2_b + i * NE, h);
        launch_mma<2>(h, fw, fc, NM, 4 * NE, NE, NE, NE, 4 * NE);
        launch_mma<3>(fc, fpw, x, NM, NE, 4 * NE, 4 * NE, 4 * NE, NE);
    }

    ln_kernel<<<NM, 256>>>(x, lnf_w, lnf_b, h);

    const size_t P = (size_t)NM * NV;
    float* out = (float*)d_out;

    if ((size_t)out_size >= P) {
        dim3 grid(NM / 128, (NV + 127) / 128);
        mma_gemm<4, 1><<<grid, 128, MMA_SMEM>>>(h, wl, out, NM, NV, NE, NE, NE, NV);
        loss_lse_kernel<<<NM / 128, 128>>>(out, targets);
        if ((size_t)out_size >= P + 1)
            loss_reduce_kernel<<<1, 256>>>(targets, out + P);
    } else {
        const int CHUNK = 1024;
        for (int c = 0; c < NM / CHUNK; c++) {
            launch_mma<0>(h + (size_t)c * CHUNK * NE, wl, att,
                          CHUNK, NV, NE, NE, NE, NV);
            loss_row_kernel<<<CHUNK, 256>>>(att, targets, c * CHUNK, NV);
        }
        int li = (out_size >= 1) ? out_size - 1 : 0;
        loss_reduce_kernel<<<1, 256>>>(targets, out + li);
    }
}